// round 15
// baseline (speedup 1.0000x reference)
#include <cuda_runtime.h>
#include <cstdint>

// Problem constants
#define NN    8192
#define NP1   8193
#define AB    16384ULL                    // A_low base (floats)
#define MM    67125249ULL                 // NP1*NP1
#define AUB   67141633ULL                 // A_up base = AB + MM
#define LR0   134258689ULL                // A_up last-row start (floats)

// Sequential memset halves (bytes):
//   ms_a: A_low region  [AB*4,  AUB*4)   = 268,500,996 B
//   ms_b: A_up interior [AUB*4, LR0*4)   = 268,468,224 B
#define MSA_OFF  (AB  * 4ULL)
#define MSA_LEN  ((AUB - AB)  * 4ULL)
#define MSB_OFF  (AUB * 4ULL)
#define MSB_LEN  ((LR0 - AUB) * 4ULL)

// Edges kernel (disjoint from both memset ranges; overlaps everything):
//   [0, 16384)      : conc_low | conc_up head
//   [16384, 24577)  : A_up last row col 0..8192 (col 8192 -> 1)
#define E_HEAD  16384
#define E_TOT   (E_HEAD + NP1)            // 24577

#define THREADS 512

__global__ void __launch_bounds__(THREADS) relu_patch_edges(
        const float* __restrict__ lower,
        const float* __restrict__ upper,
        const float* __restrict__ alphas,
        float* __restrict__ out) {
    const int w = blockIdx.x * THREADS + threadIdx.x;
    if (w >= E_TOT) return;

    if (w < E_HEAD) {
        const int i = w & (NN - 1);
        const float l = lower[i];
        const float u = upper[i];
        float val;
        if (w < NN) {
            const float a = fminf(fmaxf(alphas[i], 0.f), 1.f);
            val = (u > 0.f) ? ((l >= 0.f) ? l : a * l) : 0.f;
        } else {
            val = (u > 0.f) ? u : 0.f;
        }
        out[w] = val;
    } else {
        const int col = w - E_HEAD;
        float val;
        if (col == NN) {
            val = 1.f;
        } else {
            const float l = lower[col];
            const float u = upper[col];
            const float d = u - l;
            const float lam = u / ((d == 0.f) ? 1.f : d);
            val = ((u > 0.f) && (l < 0.f)) ? (-lam * l) : 0.f;
        }
        out[LR0 + (size_t)col] = val;
    }
}

// A_low diagonal: k = 0..8192 (k = 8192 -> 1). Positions all inside ms_a range.
// Runs on a side stream, overlapped with ms_b.
__global__ void __launch_bounds__(THREADS) relu_patch_diag_low(
        const float* __restrict__ lower,
        const float* __restrict__ upper,
        const float* __restrict__ alphas,
        float* __restrict__ out) {
    const int k = blockIdx.x * THREADS + threadIdx.x;
    if (k > NN) return;
    float val;
    if (k == NN) {
        val = 1.f;
    } else {
        const float l = lower[k];
        const float u = upper[k];
        const float a = fminf(fmaxf(alphas[k], 0.f), 1.f);
        val = (u > 0.f) ? ((l >= 0.f) ? 1.f : a) : 0.f;
    }
    __stcs(out + AB + (size_t)k * (size_t)(NP1 + 1), val);
}

// A_up diagonal: k = 0..8191. Positions inside ms_b range. Serialized tail.
__global__ void __launch_bounds__(THREADS) relu_patch_diag_up(
        const float* __restrict__ lower,
        const float* __restrict__ upper,
        float* __restrict__ out) {
    const int k = blockIdx.x * THREADS + threadIdx.x;
    if (k >= NN) return;
    const float l = lower[k];
    const float u = upper[k];
    const float d = u - l;
    const float lam = u / ((d == 0.f) ? 1.f : d);
    const float val = (u > 0.f) ? ((l >= 0.f) ? 1.f : lam) : 0.f;
    __stcs(out + AUB + (size_t)k * (size_t)(NP1 + 1), val);
}

// Streams/events created once at load; no device-memory allocation.
namespace {
struct ForkCtx {
    cudaStream_t sD, sE;
    cudaEvent_t  eRoot, eMsA, eDlow, eE;
    ForkCtx() {
        cudaStreamCreateWithFlags(&sD, cudaStreamNonBlocking);
        cudaStreamCreateWithFlags(&sE, cudaStreamNonBlocking);
        cudaEventCreateWithFlags(&eRoot, cudaEventDisableTiming);
        cudaEventCreateWithFlags(&eMsA,  cudaEventDisableTiming);
        cudaEventCreateWithFlags(&eDlow, cudaEventDisableTiming);
        cudaEventCreateWithFlags(&eE,    cudaEventDisableTiming);
    }
};
ForkCtx g_f;
}

extern "C" void kernel_launch(void* const* d_in, const int* in_sizes, int n_in,
                              void* d_out, int out_size) {
    const float* lower  = (const float*)d_in[0];
    const float* upper  = (const float*)d_in[1];
    const float* alphas = (const float*)d_in[2];
    float* out = (float*)d_out;
    char*  base = (char*)d_out;

    // Edges kernel: fully disjoint bytes -> overlaps both memset halves.
    cudaEventRecord(g_f.eRoot, 0);
    cudaStreamWaitEvent(g_f.sE, g_f.eRoot, 0);
    relu_patch_edges<<<(E_TOT + THREADS - 1) / THREADS, THREADS, 0, g_f.sE>>>(
        lower, upper, alphas, out);
    cudaEventRecord(g_f.eE, g_f.sE);

    // ms_a: zero the A_low region (stream 0).
    cudaMemsetAsync(base + MSA_OFF, 0, MSA_LEN, 0);
    cudaEventRecord(g_f.eMsA, 0);

    // diag_low patches the A_low diagonal on a side stream, CONCURRENT with ms_b.
    cudaStreamWaitEvent(g_f.sD, g_f.eMsA, 0);
    relu_patch_diag_low<<<(NP1 + THREADS - 1) / THREADS, THREADS, 0, g_f.sD>>>(
        lower, upper, alphas, out);
    cudaEventRecord(g_f.eDlow, g_f.sD);

    // ms_b: zero the A_up interior (stream 0).
    cudaMemsetAsync(base + MSB_OFF, 0, MSB_LEN, 0);

    // Serialized tail: A_up diagonal only (8192 stores).
    relu_patch_diag_up<<<(NN + THREADS - 1) / THREADS, THREADS>>>(
        lower, upper, out);

    // Joins before capture ends.
    cudaStreamWaitEvent(0, g_f.eDlow, 0);
    cudaStreamWaitEvent(0, g_f.eE, 0);
}

// round 16
// speedup vs baseline: 1.0458x; 1.0458x over previous
#include <cuda_runtime.h>
#include <cstdint>

// Problem constants
#define NN    8192
#define NP1   8193
#define AB    16384ULL                    // A_low base (floats)
#define MM    67125249ULL                 // NP1*NP1 floats per matrix
#define AUB   67141633ULL                 // A_up base = AB + MM
#define LR0   134258689ULL                // A_up last-row start (floats)

// Flat patch segments (one store per thread; best-measured config: 512t x 81 blocks):
//   [0, 16384)      : conc_low | conc_up head     (coalesced)
//   [16384, 24577)  : A_up last row col 0..8192   (coalesced; col 8192 -> 1)
//   [24577, 32770)  : A_low diagonal k = 0..8192  (scattered; k 8192 -> 1)
//   [32770, 40962)  : A_up diagonal  k = 0..8191  (scattered)
#define W_HEAD   16384
#define W_LROW   (W_HEAD + NP1)           // 24577
#define W_DLOW   (W_LROW + NP1)           // 32770
#define W_TOT    (W_DLOW + NN)            // 40962

#define THREADS 512

__global__ void __launch_bounds__(THREADS) relu_relax_patch(
        const float* __restrict__ lower,
        const float* __restrict__ upper,
        const float* __restrict__ alphas,
        float* __restrict__ out) {
    const int w = blockIdx.x * THREADS + threadIdx.x;
    if (w >= W_TOT) return;

    if (w < W_HEAD) {
        // conc_low / conc_up (coalesced)
        const int i = w & (NN - 1);
        const float l = lower[i];
        const float u = upper[i];
        float val;
        if (w < NN) {
            const float a = fminf(fmaxf(alphas[i], 0.f), 1.f);
            val = (u > 0.f) ? ((l >= 0.f) ? l : a * l) : 0.f;
        } else {
            val = (u > 0.f) ? u : 0.f;
        }
        out[w] = val;
        return;
    }

    if (w < W_LROW) {
        // A_up last row (bias_up); col NN -> 1.0 (coalesced)
        const int col = w - W_HEAD;
        float val;
        if (col == NN) {
            val = 1.f;
        } else {
            const float l = lower[col];
            const float u = upper[col];
            const float d = u - l;
            const float lam = u / ((d == 0.f) ? 1.f : d);
            val = ((u > 0.f) && (l < 0.f)) ? (-lam * l) : 0.f;
        }
        out[LR0 + (size_t)col] = val;
        return;
    }

    // Scattered diagonal segments (one streaming store per thread).
    size_t pos;
    float  val;
    if (w < W_DLOW) {
        const int k = w - W_LROW;                     // A_low diag, k = 0..8192
        if (k == NN) {
            val = 1.f;
        } else {
            const float l = lower[k];
            const float u = upper[k];
            const float a = fminf(fmaxf(alphas[k], 0.f), 1.f);
            val = (u > 0.f) ? ((l >= 0.f) ? 1.f : a) : 0.f;
        }
        pos = AB + (size_t)k * (size_t)(NP1 + 1);
    } else {
        const int k = w - W_DLOW;                     // A_up diag, k = 0..8191
        const float l = lower[k];
        const float u = upper[k];
        const float d = u - l;
        const float lam = u / ((d == 0.f) ? 1.f : d);
        val = (u > 0.f) ? ((l >= 0.f) ? 1.f : lam) : 0.f;
        pos = AUB + (size_t)k * (size_t)(NP1 + 1);
    }
    __stcs(out + pos, val);
}

extern "C" void kernel_launch(void* const* d_in, const int* in_sizes, int n_in,
                              void* d_out, int out_size) {
    const float* lower  = (const float*)d_in[0];
    const float* upper  = (const float*)d_in[1];
    const float* alphas = (const float*)d_in[2];
    float* out = (float*)d_out;

    // Minimal critical path: one full-buffer memset node (fast-mode ~7.4 TB/s;
    // mode is a per-run GPU state draw, shape-independent — R1/R4..R15 ledger)
    // followed by ONE patch kernel (~5 us, dominated by fixed node overhead).
    // Every multi-node alternative measured slower (R12: 82.0, R14: 81.0,
    // R15: 84.1); SM-side bulk fills cap at ~5.6 TB/s (R2/R3/R9: 87.7+).
    cudaMemsetAsync(d_out, 0, (size_t)out_size * sizeof(float), 0);

    const int blocks = (W_TOT + THREADS - 1) / THREADS;   // 81
    relu_relax_patch<<<blocks, THREADS>>>(lower, upper, alphas, out);
}

// round 17
// speedup vs baseline: 1.0576x; 1.0113x over previous
#include <cuda_runtime.h>
#include <cstdint>

// Problem constants
#define NN    8192
#define NP1   8193
#define AB    16384ULL                    // A_low base (floats)
#define MM    67125249ULL                 // NP1*NP1
#define AUB   67141633ULL                 // A_up base = AB + MM
#define LR0   134258689ULL                // A_up last-row start (floats)
#define ZPOS  134258688ULL                // lone interior zero not covered by ms_b

// Pitched memsets: in each matrix region the diagonal has period 8194 floats
// and sits at pitched-column 0. Zero columns [1, 8194) of each pitched row:
//   ms_a: dst = AB+1,  pitch = 8194*4, width = 8193*4, height = 8192
//         covers all non-diag floats of [AB, AUB-1); AUB-1 is diag corner.
//   ms_b: dst = AUB+1, pitch = 8194*4, width = 8193*4, height = 8191
//         covers non-diag of [AUB, ZPOS); ZPOS zeroed by the patch kernel.
#define PITCH_B  32776ULL                 // 8194 * 4
#define WIDTH_B  32772ULL                 // 8193 * 4

// Patch kernel (ALL bytes disjoint from the pitched memsets -> full overlap):
//   [0, 16384)      : conc_low | conc_up head
//   [16384, 24578)  : t==0 -> out[ZPOS]=0 ; else A_up last row col t-1 (col 8192 -> 1)
//   [24578, 32771)  : A_low diagonal k = 0..8192 (k = 8192 -> corner 1)
//   [32771, 40963)  : A_up diagonal  k = 0..8191
#define W_HEAD   16384
#define W_LROW   (W_HEAD + NP1 + 1)       // 24578
#define W_DLOW   (W_LROW + NP1)           // 32771
#define W_TOT    (W_DLOW + NN)            // 40963

#define THREADS 512

__global__ void __launch_bounds__(THREADS) relu_relax_patch(
        const float* __restrict__ lower,
        const float* __restrict__ upper,
        const float* __restrict__ alphas,
        float* __restrict__ out) {
    const int w = blockIdx.x * THREADS + threadIdx.x;
    if (w >= W_TOT) return;

    if (w < W_HEAD) {
        // conc_low / conc_up (coalesced)
        const int i = w & (NN - 1);
        const float l = lower[i];
        const float u = upper[i];
        float val;
        if (w < NN) {
            const float a = fminf(fmaxf(alphas[i], 0.f), 1.f);
            val = (u > 0.f) ? ((l >= 0.f) ? l : a * l) : 0.f;
        } else {
            val = (u > 0.f) ? u : 0.f;
        }
        out[w] = val;
        return;
    }

    if (w < W_LROW) {
        // ZPOS zero + A_up last row (coalesced; col 8192 -> 1.0)
        const int t = w - W_HEAD;
        float val;
        if (t == 0) {
            val = 0.f;                                 // out[ZPOS]
        } else {
            const int col = t - 1;
            if (col == NN) {
                val = 1.f;
            } else {
                const float l = lower[col];
                const float u = upper[col];
                const float d = u - l;
                const float lam = u / ((d == 0.f) ? 1.f : d);
                val = ((u > 0.f) && (l < 0.f)) ? (-lam * l) : 0.f;
            }
        }
        out[ZPOS + (size_t)t] = val;
        return;
    }

    // Diagonals (scattered streaming stores; bytes excluded from the memsets).
    size_t pos;
    float  val;
    if (w < W_DLOW) {
        const int k = w - W_LROW;                     // A_low diag, k = 0..8192
        if (k == NN) {
            val = 1.f;                                // corner A_low[N][N]
        } else {
            const float l = lower[k];
            const float u = upper[k];
            const float a = fminf(fmaxf(alphas[k], 0.f), 1.f);
            val = (u > 0.f) ? ((l >= 0.f) ? 1.f : a) : 0.f;
        }
        pos = AB + (size_t)k * (size_t)(NP1 + 1);
    } else {
        const int k = w - W_DLOW;                     // A_up diag, k = 0..8191
        const float l = lower[k];
        const float u = upper[k];
        const float d = u - l;
        const float lam = u / ((d == 0.f) ? 1.f : d);
        val = (u > 0.f) ? ((l >= 0.f) ? 1.f : lam) : 0.f;
        pos = AUB + (size_t)k * (size_t)(NP1 + 1);
    }
    __stcs(out + pos, val);
}

// Streams/events created once at load; no device-memory allocation.
namespace {
struct ForkCtx {
    cudaStream_t sM, sP;
    cudaEvent_t  eRoot, eM, eP;
    ForkCtx() {
        cudaStreamCreateWithFlags(&sM, cudaStreamNonBlocking);
        cudaStreamCreateWithFlags(&sP, cudaStreamNonBlocking);
        cudaEventCreateWithFlags(&eRoot, cudaEventDisableTiming);
        cudaEventCreateWithFlags(&eM,    cudaEventDisableTiming);
        cudaEventCreateWithFlags(&eP,    cudaEventDisableTiming);
    }
};
ForkCtx g_f;
}

extern "C" void kernel_launch(void* const* d_in, const int* in_sizes, int n_in,
                              void* d_out, int out_size) {
    const float* lower  = (const float*)d_in[0];
    const float* upper  = (const float*)d_in[1];
    const float* alphas = (const float*)d_in[2];
    float* out = (float*)d_out;
    char*  base = (char*)d_out;

    // Fork root
    cudaEventRecord(g_f.eRoot, 0);
    cudaStreamWaitEvent(g_f.sM, g_f.eRoot, 0);
    cudaStreamWaitEvent(g_f.sP, g_f.eRoot, 0);

    // Two PARALLEL pitched memsets that skip the diagonal bytes entirely.
    cudaMemset2DAsync(base + (AB + 1) * 4,  PITCH_B, 0, WIDTH_B, 8192, 0);       // A_low
    cudaMemset2DAsync(base + (AUB + 1) * 4, PITCH_B, 0, WIDTH_B, 8191, g_f.sM);  // A_up

    // Patch kernel: byte-disjoint from both memsets -> fully overlapped.
    relu_relax_patch<<<(W_TOT + THREADS - 1) / THREADS, THREADS, 0, g_f.sP>>>(
        lower, upper, alphas, out);
    cudaEventRecord(g_f.eP, g_f.sP);

    // Joins before capture ends.
    cudaEventRecord(g_f.eM, g_f.sM);
    cudaStreamWaitEvent(0, g_f.eM, 0);
    cudaStreamWaitEvent(0, g_f.eP, 0);
}